// round 12
// baseline (speedup 1.0000x reference)
#include <cuda_runtime.h>

#define NQ  16
#define DIM 65536
#define NB  64
#define NC  23
#define TPB 256
#define NPAIR 4096   // float4 pairs per 64KB tile

// wire->amp-bit map sigma: w15->0 w11->1 w10->2 w9->3 w8->4 w7->5 w12->6 w13->7
//                          w14->8 w4->9 w5->10 w6->11 w3->12 w0->13 w1->14 w2->15
__device__ float2 g_state[NB * DIM];   // 32 MB scratch
__device__ float  g_expv[NB * NQ];
__device__ int    g_cnt[NB];

struct P2 { float2 lo, hi; };          // lo: amp bit0=0 (wire15=0), hi: bit0=1

__device__ __forceinline__ float2 cmulf(float2 a, float2 b){
    return make_float2(a.x*b.x - a.y*b.y, a.x*b.y + a.y*b.x);
}
__device__ __forceinline__ void ap1q(float2 &v0, float2 &v1,
                                     float2 u00, float2 u01, float2 u10, float2 u11){
    float2 a = v0, b = v1;
    v0.x = u00.x*a.x - u00.y*a.y + u01.x*b.x - u01.y*b.y;
    v0.y = u00.x*a.y + u00.y*a.x + u01.x*b.y + u01.y*b.x;
    v1.x = u10.x*a.x - u10.y*a.y + u11.x*b.x - u11.y*b.y;
    v1.y = u10.x*a.y + u10.y*a.x + u11.x*b.y + u11.y*b.x;
}
// RX(theta): [[c, -i s], [-i s, c]] with c=cos(t/2), s=sin(t/2)
__device__ __forceinline__ void aprx(float2 &v0, float2 &v1, float c, float s){
    float2 a = v0, b = v1;
    v0 = make_float2(fmaf(c, a.x,  s*b.y), fmaf(c, a.y, -s*b.x));
    v1 = make_float2(fmaf(c, b.x,  s*a.y), fmaf(c, b.y, -s*a.x));
}
__device__ __forceinline__ int FP(int p){ return p ^ ((p>>3)&7) ^ ((p>>6)&7); }

__device__ __forceinline__ P2 ld4(const float4* S, int i){
    float4 t = S[i]; P2 r; r.lo = make_float2(t.x,t.y); r.hi = make_float2(t.z,t.w); return r;
}
__device__ __forceinline__ void st4(float4* S, int i, P2 v){
    S[i] = make_float4(v.lo.x, v.lo.y, v.hi.x, v.hi.y);
}

// Fused U = Rot(w[q]) * RX(x[b,q]); CRX params (cos, sin) of half-angle.
__device__ __forceinline__ void setup_one(const float* __restrict__ x,
                                          const float* __restrict__ w,
                                          const float* __restrict__ xc,
                                          int b, int q, float2 (*sU)[4], float2* sCX){
    float xv = x[b*NQ + q];
    float hc = cosf(0.5f*xv), hs = sinf(0.5f*xv);
    float phi = w[q*3+0], th = w[q*3+1], om = w[q*3+2];
    float ct = cosf(0.5f*th), st = sinf(0.5f*th);
    float pp = 0.5f*(phi+om), mm = 0.5f*(phi-om);
    float2 A  = make_float2( cosf(pp)*ct, -sinf(pp)*ct);
    float2 Bm = make_float2(-cosf(mm)*st, -sinf(mm)*st);
    float2 C  = make_float2( cosf(mm)*st, -sinf(mm)*st);
    float2 D  = make_float2( cosf(pp)*ct,  sinf(pp)*ct);
    sU[q][0] = make_float2(A.x*hc + Bm.y*hs,   A.y*hc - Bm.x*hs);
    sU[q][1] = make_float2(A.y*hs + Bm.x*hc,  -A.x*hs + Bm.y*hc);
    sU[q][2] = make_float2(C.x*hc + D.y*hs,    C.y*hc - D.x*hs);
    sU[q][3] = make_float2(C.y*hs + D.x*hc,   -C.x*hs + D.y*hc);
    float cv = xc[q];
    sCX[q] = make_float2(cosf(0.5f*cv), sinf(0.5f*cv));
}

// ---- gate helpers on P2 arrays ----
template<int N, int K>
__device__ __forceinline__ void g1q(P2* v, const float2* u){
    float2 u00 = u[0], u01 = u[1], u10 = u[2], u11 = u[3];
    #pragma unroll
    for (int m = 0; m < N; m++)
        if (!(m & (1 << K))){
            ap1q(v[m].lo, v[m | (1 << K)].lo, u00, u01, u10, u11);
            ap1q(v[m].hi, v[m | (1 << K)].hi, u00, u01, u10, u11);
        }
}
template<int N, int KC, int KT>
__device__ __forceinline__ void gcrx(P2* v, float2 cs){
    #pragma unroll
    for (int m = 0; m < N; m++)
        if ((m & (1 << KC)) && !(m & (1 << KT))){
            aprx(v[m].lo, v[m | (1 << KT)].lo, cs.x, cs.y);
            aprx(v[m].hi, v[m | (1 << KT)].hi, cs.x, cs.y);
        }
}
template<int N>
__device__ __forceinline__ void g1q_pair(P2* v, const float2* u){
    float2 u00 = u[0], u01 = u[1], u10 = u[2], u11 = u[3];
    #pragma unroll
    for (int m = 0; m < N; m++) ap1q(v[m].lo, v[m].hi, u00, u01, u10, u11);
}
template<int N, int KC>
__device__ __forceinline__ void gcrx_tgtpair(P2* v, float2 cs){
    #pragma unroll
    for (int m = 0; m < N; m++)
        if (m & (1 << KC)) aprx(v[m].lo, v[m].hi, cs.x, cs.y);
}
template<int N, int KT>
__device__ __forceinline__ void gcrx_ctrlpair(P2* v, float2 cs){
    #pragma unroll
    for (int m = 0; m < N; m++)
        if (!(m & (1 << KT))) aprx(v[m].hi, v[m | (1 << KT)].hi, cs.x, cs.y);
}

// ---------------------------------------------------------------------------
// P1: analytic init (all 16 L1 1q + L1 CRX0,1,2 via tables) + L1 CRX3..14
//     + fused L2 1q w3..w14.  Tile t = amp bits {13,14,15} (w0,w1,w2).
//     Locals = amp bits 12..0; pair p = amp bits 12..1.  Write-only.
// p-bit -> wire: p0..p7 = w11,w10,w9,w8,w7,w12,w13,w14; p8=w4 p9=w5 p10=w6 p11=w3
// Rounds restructured to v8 (3 ext bits) to stay under the 128-reg cap:
//  r1{11,8,9}: CRX3,4 + w3,w4     r2{9,10,4}: CRX5,6 + w5,w6
//  r3{4,3,2}:  CRX7,8 + w7,w8     r4{2,1,0}:  CRX9,10 + w9,w10
//  r5{0,5,6}:  CRX11,12 + w11,w12 r6{6,7}+pair: CRX13,14 + w13,w14
// ---------------------------------------------------------------------------
__global__ void __launch_bounds__(TPB, 2)
p1_init(const float* __restrict__ x, const float* __restrict__ w0,
        const float* __restrict__ x0, const float* __restrict__ w1,
        const float* __restrict__ x1){
    extern __shared__ float4 S[];
    __shared__ float2 sU1[NQ][4], sU2[NQ][4];
    __shared__ float2 sCX1[NQ], sCX2d[NQ];
    __shared__ float2 sT4x[16];
    __shared__ float2 sTb[8];
    __shared__ float4 sTa[256];
    int tid = threadIdx.x, t = blockIdx.x, b = blockIdx.y;
    if (tid < 16)      setup_one(x, w0, x0, b, tid,      sU1, sCX1);
    else if (tid < 32) setup_one(x, w1, x1, b, tid - 16, sU2, sCX2d);
    if (t == 0 && tid >= 32 && tid < 48) g_expv[b*NQ + (tid-32)] = 0.f;
    if (t == 0 && tid == 48) g_cnt[b] = 0;
    __syncthreads();

    // Ta over amp bits 1..8 (wires 11,10,9,8,7,12,13,14) + pair (w15)
    {
        int s8 = tid;
        float2 a = sU1[11][(s8&1)?2:0];
        a = cmulf(a, sU1[10][((s8>>1)&1)?2:0]);
        a = cmulf(a, sU1[ 9][((s8>>2)&1)?2:0]);
        a = cmulf(a, sU1[ 8][((s8>>3)&1)?2:0]);
        a = cmulf(a, sU1[ 7][((s8>>4)&1)?2:0]);
        a = cmulf(a, sU1[12][((s8>>5)&1)?2:0]);
        a = cmulf(a, sU1[13][((s8>>6)&1)?2:0]);
        a = cmulf(a, sU1[14][((s8>>7)&1)?2:0]);
        float2 lo = cmulf(a, sU1[15][0]);
        float2 hi = cmulf(a, sU1[15][2]);
        sTa[s8] = make_float4(lo.x, lo.y, hi.x, hi.y);
    }
    if (tid < 8){   // Tb over amp bits 9,10,11 (wires 4,5,6): j2=b9 j1=b10 j0=b11
        int j = tid;
        float2 a2 = cmulf(sU1[4][((j>>2)&1)?2:0], sU1[5][((j>>1)&1)?2:0]);
        sTb[j] = cmulf(a2, sU1[6][(j&1)?2:0]);
    }
    if (tid >= 16 && tid < 32){  // T4x over (w0,w1,w2,w3): m3=w0 m2=w1 m1=w2 m0=w3
        int m = tid - 16;
        float2 a2 = cmulf(sU1[0][((m>>3)&1)?2:0], sU1[1][((m>>2)&1)?2:0]);
        a2 = cmulf(a2, sU1[2][((m>>1)&1)?2:0]);
        sT4x[m] = cmulf(a2, sU1[3][(m&1)?2:0]);
    }
    __syncthreads();
    if (tid < 4){ float2 cs = sCX1[0]; aprx(sT4x[8+tid], sT4x[12+tid], cs.x, cs.y); }
    __syncthreads();
    if (tid < 4){ float2 cs = sCX1[1]; int m = (tid&1) | ((tid>>1)<<3) | 4;
                  aprx(sT4x[m], sT4x[m|2], cs.x, cs.y); }
    __syncthreads();
    if (tid < 4){ float2 cs = sCX1[2]; int m = 2 + 4*tid;
                  aprx(sT4x[m], sT4x[m|1], cs.x, cs.y); }
    __syncthreads();

    // Fill tile: t bit0 = amp13(w0), bit1 = amp14(w1), bit2 = amp15(w2)
    #pragma unroll
    for (int k = 0; k < 16; k++){
        int p = tid + (k << 8);
        int m = ((t&1)<<3) | (((t>>1)&1)<<2) | (((t>>2)&1)<<1) | ((p>>11)&1);
        int j = (((p>>8)&1)<<2) | (((p>>9)&1)<<1) | ((p>>10)&1);
        float2 c = cmulf(sT4x[m], sTb[j]);
        float4 ta = sTa[p & 255];
        P2 v;
        v.lo = cmulf(c, make_float2(ta.x, ta.y));
        v.hi = cmulf(c, make_float2(ta.z, ta.w));
        st4(S, FP(p), v);
    }
    __syncthreads();

    // r1 v8 ext: m2=p11(w3) m1=p8(w4) m0=p9(w5) : CRX3, 1q w3, CRX4, 1q w4
    #pragma unroll
    for (int it = 0; it < 2; it++){
      P2 v[8]; int g = tid + (it<<8);
      int base = (g & 255) | (((g>>8)&1)<<10);
      #pragma unroll
      for (int m = 0; m < 8; m++){
        int p = base | (((m>>2)&1)<<11) | (((m>>1)&1)<<8) | ((m&1)<<9);
        v[m] = ld4(S, FP(p));
      }
      gcrx<8,2,1>(v, sCX1[3]); g1q<8,2>(v, sU2[3]);
      gcrx<8,1,0>(v, sCX1[4]); g1q<8,1>(v, sU2[4]);
      #pragma unroll
      for (int m = 0; m < 8; m++){
        int p = base | (((m>>2)&1)<<11) | (((m>>1)&1)<<8) | ((m&1)<<9);
        st4(S, FP(p), v[m]);
      }
    }
    __syncthreads();
    // r2 v8 ext: m2=p9(w5) m1=p10(w6) m0=p4(w7) : CRX5, 1q w5, CRX6, 1q w6
    #pragma unroll
    for (int it = 0; it < 2; it++){
      P2 v[8]; int g = tid + (it<<8);
      int base = (g & 15) | (((g>>4)&7)<<5) | (((g>>7)&1)<<8) | (((g>>8)&1)<<11);
      #pragma unroll
      for (int m = 0; m < 8; m++){
        int p = base | (((m>>2)&1)<<9) | (((m>>1)&1)<<10) | ((m&1)<<4);
        v[m] = ld4(S, FP(p));
      }
      gcrx<8,2,1>(v, sCX1[5]); g1q<8,2>(v, sU2[5]);
      gcrx<8,1,0>(v, sCX1[6]); g1q<8,1>(v, sU2[6]);
      #pragma unroll
      for (int m = 0; m < 8; m++){
        int p = base | (((m>>2)&1)<<9) | (((m>>1)&1)<<10) | ((m&1)<<4);
        st4(S, FP(p), v[m]);
      }
    }
    __syncthreads();
    // r3 v8 ext: m2=p4(w7) m1=p3(w8) m0=p2(w9) : CRX7, 1q w7, CRX8, 1q w8
    #pragma unroll
    for (int it = 0; it < 2; it++){
      P2 v[8]; int g = tid + (it<<8);
      int base = (g & 3) | ((g >> 2) << 5);
      #pragma unroll
      for (int m = 0; m < 8; m++){
        int p = base | (((m>>2)&1)<<4) | (((m>>1)&1)<<3) | ((m&1)<<2);
        v[m] = ld4(S, FP(p));
      }
      gcrx<8,2,1>(v, sCX1[7]); g1q<8,2>(v, sU2[7]);
      gcrx<8,1,0>(v, sCX1[8]); g1q<8,1>(v, sU2[8]);
      #pragma unroll
      for (int m = 0; m < 8; m++){
        int p = base | (((m>>2)&1)<<4) | (((m>>1)&1)<<3) | ((m&1)<<2);
        st4(S, FP(p), v[m]);
      }
    }
    __syncthreads();
    // r4 v8 ext: m2=p2(w9) m1=p1(w10) m0=p0(w11) : CRX9, 1q w9, CRX10, 1q w10
    #pragma unroll
    for (int it = 0; it < 2; it++){
      P2 v[8]; int g = tid + (it<<8);
      int base = g << 3;
      #pragma unroll
      for (int m = 0; m < 8; m++){
        int p = base | (((m>>2)&1)<<2) | (((m>>1)&1)<<1) | (m&1);
        v[m] = ld4(S, FP(p));
      }
      gcrx<8,2,1>(v, sCX1[9]);  g1q<8,2>(v, sU2[9]);
      gcrx<8,1,0>(v, sCX1[10]); g1q<8,1>(v, sU2[10]);
      #pragma unroll
      for (int m = 0; m < 8; m++){
        int p = base | (((m>>2)&1)<<2) | (((m>>1)&1)<<1) | (m&1);
        st4(S, FP(p), v[m]);
      }
    }
    __syncthreads();
    // r5 v8 ext: m2=p0(w11) m1=p5(w12) m0=p6(w13) : CRX11, 1q w11, CRX12, 1q w12
    #pragma unroll
    for (int it = 0; it < 2; it++){
      P2 v[8]; int g = tid + (it<<8);
      int base = ((g & 15) << 1) | ((g >> 4) << 7);
      #pragma unroll
      for (int m = 0; m < 8; m++){
        int p = base | ((m>>2)&1) | (((m>>1)&1)<<5) | ((m&1)<<6);
        v[m] = ld4(S, FP(p));
      }
      gcrx<8,2,1>(v, sCX1[11]); g1q<8,2>(v, sU2[11]);
      gcrx<8,1,0>(v, sCX1[12]); g1q<8,1>(v, sU2[12]);
      #pragma unroll
      for (int m = 0; m < 8; m++){
        int p = base | ((m>>2)&1) | (((m>>1)&1)<<5) | ((m&1)<<6);
        st4(S, FP(p), v[m]);
      }
    }
    __syncthreads();
    // r6 v4 ext: m1=p6(w13) m0=p7(w14), pair=w15 : CRX13, 1q w13, CRX14, 1q w14
    #pragma unroll
    for (int it = 0; it < 4; it++){
      P2 v[4]; int g = tid + (it<<8);
      int base = (g & 63) | ((g >> 6) << 8);
      #pragma unroll
      for (int m = 0; m < 4; m++){
        int p = base | (((m>>1)&1)<<6) | ((m&1)<<7);
        v[m] = ld4(S, FP(p));
      }
      gcrx<4,1,0>(v, sCX1[13]); g1q<4,1>(v, sU2[13]);
      gcrx_tgtpair<4,0>(v, sCX1[14]); g1q<4,0>(v, sU2[14]);
      #pragma unroll
      for (int m = 0; m < 4; m++){
        int p = base | (((m>>1)&1)<<6) | ((m&1)<<7);
        st4(S, FP(p), v[m]);
      }
    }
    __syncthreads();

    float4* go = (float4*)(g_state + b*DIM) + (t << 12);
    #pragma unroll
    for (int k = 0; k < 16; k++){ int p = tid + (k << 8); go[p] = S[FP(p)]; }
}

// ---------------------------------------------------------------------------
// P2: L1 CRX15 + L2 1q w15,w0,w1,w2 + L2 CRX0..7.  (unchanged from R10)
// ---------------------------------------------------------------------------
__global__ void __launch_bounds__(TPB, 2)
p2_mid(const float* __restrict__ x, const float* __restrict__ x0,
       const float* __restrict__ w1, const float* __restrict__ x1){
    extern __shared__ float4 S[];
    __shared__ float2 sU2[NQ][4], sCX2[NQ];
    __shared__ float2 c15s;
    int tid = threadIdx.x, t = blockIdx.x, b = blockIdx.y;
    if (tid < 16) setup_one(x, w1, x1, b, tid, sU2, sCX2);
    else if (tid == 16){
        float cv = x0[15];
        c15s = make_float2(cosf(0.5f*cv), sinf(0.5f*cv));
    }
    __syncthreads();

    const float4* g4 = (const float4*)(g_state + b*DIM);
    #pragma unroll
    for (int k = 0; k < 16; k++){
        int p = tid + (k << 8);
        int pr = (p & 31) | (t << 5) | ((p >> 5) << 8);
        S[FP(p)] = g4[pr];
    }
    __syncthreads();

    // r0 v8 ext: m2=p9(w0) m1=p10(w1) m0=p11(w2), pair=w15
    {
      float2 c15 = c15s;
      #pragma unroll
      for (int it = 0; it < 2; it++){
        P2 v[8]; int g = tid + (it<<8);
        #pragma unroll
        for (int m = 0; m < 8; m++){
          int p = g | (((m>>2)&1)<<9) | (((m>>1)&1)<<10) | ((m&1)<<11);
          v[m] = ld4(S, FP(p));
        }
        gcrx_ctrlpair<8,2>(v, c15);          // CRX15(L1): w15 -> w0
        g1q_pair<8>(v, sU2[15]);
        g1q<8,2>(v, sU2[0]); g1q<8,1>(v, sU2[1]); g1q<8,0>(v, sU2[2]);
        gcrx<8,2,1>(v, sCX2[0]);             // CRX0(L2)
        gcrx<8,1,0>(v, sCX2[1]);             // CRX1(L2)
        #pragma unroll
        for (int m = 0; m < 8; m++){
          int p = g | (((m>>2)&1)<<9) | (((m>>1)&1)<<10) | ((m&1)<<11);
          st4(S, FP(p), v[m]);
        }
      }
    }
    __syncthreads();
    // r1 v16 ext: m3=p11(w2) m2=p8(w3) m1=p5(w4) m0=p6(w5) : CRX2,3,4
    { P2 v[16]; int g = tid;
      int base = (g & 31) | (((g>>5)&1)<<7) | (((g>>6)&3)<<9);
      #pragma unroll
      for (int m = 0; m < 16; m++){
        int p = base | (((m>>3)&1)<<11) | (((m>>2)&1)<<8) | (((m>>1)&1)<<5) | ((m&1)<<6);
        v[m] = ld4(S, FP(p));
      }
      gcrx<16,3,2>(v, sCX2[2]); gcrx<16,2,1>(v, sCX2[3]); gcrx<16,1,0>(v, sCX2[4]);
      #pragma unroll
      for (int m = 0; m < 16; m++){
        int p = base | (((m>>3)&1)<<11) | (((m>>2)&1)<<8) | (((m>>1)&1)<<5) | ((m&1)<<6);
        st4(S, FP(p), v[m]);
      }
    }
    __syncthreads();
    // r2 v16 ext: m3=p6(w5) m2=p7(w6) m1=p4(w7) m0=p3(w8) : CRX5,6,7
    { P2 v[16]; int g = tid;
      int base = (g & 7) | (((g>>3)&1)<<5) | ((g>>4)<<8);
      #pragma unroll
      for (int m = 0; m < 16; m++){
        int p = base | (((m>>3)&1)<<6) | (((m>>2)&1)<<7) | (((m>>1)&1)<<4) | ((m&1)<<3);
        v[m] = ld4(S, FP(p));
      }
      gcrx<16,3,2>(v, sCX2[5]); gcrx<16,2,1>(v, sCX2[6]); gcrx<16,1,0>(v, sCX2[7]);
      #pragma unroll
      for (int m = 0; m < 16; m++){
        int p = base | (((m>>3)&1)<<6) | (((m>>2)&1)<<7) | (((m>>1)&1)<<4) | ((m&1)<<3);
        st4(S, FP(p), v[m]);
      }
    }
    __syncthreads();

    float4* go = (float4*)(g_state + b*DIM);
    #pragma unroll
    for (int k = 0; k < 16; k++){
        int p = tid + (k << 8);
        int pr = (p & 31) | (t << 5) | ((p >> 5) << 8);
        go[pr] = S[FP(p)];
    }
}

// ---------------------------------------------------------------------------
// P3: L2 CRX8..14 + CRX15 + expvals + last-CTA FC epilogue. (unchanged)
// ---------------------------------------------------------------------------
__global__ void __launch_bounds__(TPB, 2)
p3_final(const float* __restrict__ x1, const float* __restrict__ fc_w,
         const float* __restrict__ fc_b, float* __restrict__ out){
    extern __shared__ float4 S[];
    __shared__ float2 sCX2[NQ];
    __shared__ float sred[8][NQ];
    __shared__ int lastf;
    int tid = threadIdx.x, t = blockIdx.x, b = blockIdx.y;
    if (tid < 16){
        float cv = x1[tid];
        sCX2[tid] = make_float2(cosf(0.5f*cv), sinf(0.5f*cv));
    }
    __syncthreads();

    const float4* g4 = (const float4*)(g_state + b*DIM);
    #pragma unroll
    for (int k = 0; k < 16; k++){
        int p = tid + (k << 8);
        int pr = (p & 255) | (t << 8) | ((p >> 8) << 11);
        S[FP(p)] = g4[pr];
    }
    __syncthreads();

    // r0 v16 ext: m3=p3(w8) m2=p2(w9) m1=p1(w10) m0=p0(w11) : CRX8,9,10
    { P2 v[16]; int base = tid << 4;
      #pragma unroll
      for (int m = 0; m < 16; m++) v[m] = ld4(S, FP(base | m));
      gcrx<16,3,2>(v, sCX2[8]); gcrx<16,2,1>(v, sCX2[9]); gcrx<16,1,0>(v, sCX2[10]);
      #pragma unroll
      for (int m = 0; m < 16; m++) st4(S, FP(base | m), v[m]);
    }
    __syncthreads();
    // r1 v16 ext: m3=p0(w11) m2=p5(w12) m1=p6(w13) m0=p7(w14) : CRX11,12,13,14(pair)
    { P2 v[16]; int g = tid;
      int base = ((g & 15) << 1) | ((g >> 4) << 8);
      #pragma unroll
      for (int m = 0; m < 16; m++){
        int p = base | ((m>>3)&1) | (((m>>2)&1)<<5) | (((m>>1)&1)<<6) | ((m&1)<<7);
        v[m] = ld4(S, FP(p));
      }
      gcrx<16,3,2>(v, sCX2[11]); gcrx<16,2,1>(v, sCX2[12]);
      gcrx<16,1,0>(v, sCX2[13]); gcrx_tgtpair<16,0>(v, sCX2[14]);
      #pragma unroll
      for (int m = 0; m < 16; m++){
        int p = base | ((m>>3)&1) | (((m>>2)&1)<<5) | (((m>>1)&1)<<6) | ((m&1)<<7);
        st4(S, FP(p), v[m]);
      }
    }
    __syncthreads();

    // CRX15(L2) (ctrl pair, tgt w0 = p9) fused with expval accumulation.
    float2 c15 = sCX2[15];
    float acc[NQ];
    #pragma unroll
    for (int q = 0; q < NQ; q++) acc[q] = 0.f;
    float pstot = 0.f;
    #pragma unroll
    for (int it = 0; it < 8; it++){
        int j = tid + (it << 8);
        int p = (j & 511) | ((j >> 9) << 10);      // p9 = 0
        P2 v0 = ld4(S, FP(p));
        P2 v1 = ld4(S, FP(p | 512));
        aprx(v0.hi, v1.hi, c15.x, c15.y);
        float pA0 = v0.lo.x*v0.lo.x + v0.lo.y*v0.lo.y;
        float pA1 = v0.hi.x*v0.hi.x + v0.hi.y*v0.hi.y;
        float pB0 = v1.lo.x*v1.lo.x + v1.lo.y*v1.lo.y;
        float pB1 = v1.hi.x*v1.hi.x + v1.hi.y*v1.hi.y;
        float ps = pA0 + pA1 + pB0 + pB1;
        pstot += ps;
        acc[0]  += (pA0 + pA1) - (pB0 + pB1);      // w0  = p9
        acc[15] += (pA0 - pA1) + (pB0 - pB1);      // w15 = pair
        acc[11] += (p & 1)    ? -ps : ps;
        acc[10] += (p & 2)    ? -ps : ps;
        acc[9]  += (p & 4)    ? -ps : ps;
        acc[8]  += (p & 8)    ? -ps : ps;
        acc[7]  += (p & 16)   ? -ps : ps;
        acc[12] += (p & 32)   ? -ps : ps;
        acc[13] += (p & 64)   ? -ps : ps;
        acc[14] += (p & 128)  ? -ps : ps;
        acc[3]  += (p & 256)  ? -ps : ps;
        acc[1]  += (p & 1024) ? -ps : ps;
        acc[2]  += (p & 2048) ? -ps : ps;
    }
    acc[4] = (t & 1) ? -pstot : pstot;
    acc[5] = (t & 2) ? -pstot : pstot;
    acc[6] = (t & 4) ? -pstot : pstot;

    #pragma unroll
    for (int q = 0; q < NQ; q++){
        float v = acc[q];
        #pragma unroll
        for (int off = 16; off > 0; off >>= 1)
            v += __shfl_down_sync(0xffffffffu, v, off);
        acc[q] = v;
    }
    int w = tid >> 5, lane = tid & 31;
    if (lane == 0){
        #pragma unroll
        for (int q = 0; q < NQ; q++) sred[w][q] = acc[q];
    }
    __syncthreads();
    if (tid < NQ){
        float v = 0.f;
        #pragma unroll
        for (int w2 = 0; w2 < 8; w2++) v += sred[w2][tid];
        atomicAdd(&g_expv[b*NQ + tid], v);
    }
    __syncthreads();

    // ---- per-batch last-CTA FC + log_softmax epilogue ----
    if (tid == 0){
        __threadfence();
        int old = atomicAdd(&g_cnt[b], 1);
        lastf = (old == 7);
    }
    __syncthreads();
    if (lastf && tid < 32){
        __threadfence();      // acquire: make all CTAs' expval adds visible
        float f[NQ];
        #pragma unroll
        for (int q = 0; q < NQ; q++) f[q] = g_expv[b*NQ + q];
        float lg = -1e30f;
        if (tid < NC){
            lg = fc_b[tid];
            #pragma unroll
            for (int q = 0; q < NQ; q++) lg = fmaf(fc_w[tid*NQ + q], f[q], lg);
        }
        float mx = lg;
        #pragma unroll
        for (int off = 16; off > 0; off >>= 1)
            mx = fmaxf(mx, __shfl_xor_sync(0xffffffffu, mx, off));
        float e = (tid < NC) ? expf(lg - mx) : 0.f;
        float se = e;
        #pragma unroll
        for (int off = 16; off > 0; off >>= 1)
            se += __shfl_xor_sync(0xffffffffu, se, off);
        if (tid < NC) out[b*NC + tid] = lg - mx - logf(se);
    }
}

extern "C" void kernel_launch(void* const* d_in, const int* in_sizes, int n_in,
                              void* d_out, int out_size){
    const float* x   = (const float*)d_in[0];
    const float* w0  = (const float*)d_in[1];
    const float* x0  = (const float*)d_in[2];
    const float* w1  = (const float*)d_in[3];
    const float* x1  = (const float*)d_in[4];
    const float* fcw = (const float*)d_in[5];
    const float* fcb = (const float*)d_in[6];

    const int smem = NPAIR * sizeof(float4);   // 64 KB
    cudaFuncSetAttribute(p1_init,  cudaFuncAttributeMaxDynamicSharedMemorySize, smem);
    cudaFuncSetAttribute(p2_mid,   cudaFuncAttributeMaxDynamicSharedMemorySize, smem);
    cudaFuncSetAttribute(p3_final, cudaFuncAttributeMaxDynamicSharedMemorySize, smem);

    dim3 grid(8, NB);
    p1_init <<<grid, TPB, smem>>>(x, w0, x0, w1, x1);
    p2_mid  <<<grid, TPB, smem>>>(x, x0, w1, x1);
    p3_final<<<grid, TPB, smem>>>(x1, fcw, fcb, (float*)d_out);
}